// round 14
// baseline (speedup 1.0000x reference)
#include <cuda_runtime.h>
#include <cuda_fp16.h>
#include <cuda_bf16.h>

#define NN    20000
#define BG    100
#define PERN  200
#define EE    320000
#define ETOT  340000
#define FIN   32
#define NH    10
#define C1    320
#define C1E   340
#define DOUT  128
#define NEG_SLOPE 0.2f

// ---------------- scratch ----------------------------------------------------
__device__ __half g_XW1H[NN * C1];
__device__ float  g_S1S [NN * NH];
__device__ float  g_S1D [NN * NH];
__device__ __half g_X1H [NN * C1];
__device__ __half g_XW2H[NN * DOUT];
__device__ float  g_S2S [NN];
__device__ float  g_S2D [NN];
__device__ float  g_X2E [(NN + BG) * DOUT];
__device__ float  g_B1E [FIN * C1E];
__device__ float  g_Q2S [C1];
__device__ float  g_Q2D [C1];
__device__ __half g_W2H [DOUT * C1];
__device__ __half g_W2L [DOUT * C1];
__device__ __half g_FWH [DOUT * DOUT];
__device__ __half g_FWL [DOUT * DOUT];
__device__ int    g_DEG[NN + 32];           // [NN..NN+20) = lookback flags
__device__ int    g_ROWPTR[NN + 1];
__device__ int    g_ROWCUR[NN];
__device__ int    g_ESRT[ETOT];
__device__ int    g_BSUM[32];

__device__ __forceinline__ float leakyf(float x) { return x > 0.f ? x : NEG_SLOPE * x; }
__device__ __forceinline__ float eluf(float x)   { return x > 0.f ? x : __expf(x) - 1.f; }

__device__ __forceinline__ void bfsplit2(float x0, float x1, unsigned& h, unsigned& l) {
    __nv_bfloat162 hv = __floats2bfloat162_rn(x0, x1);
    float r0 = x0 - __bfloat162float(hv.x);
    float r1 = x1 - __bfloat162float(hv.y);
    __nv_bfloat162 lv = __floats2bfloat162_rn(r0, r1);
    h = *reinterpret_cast<unsigned*>(&hv);
    l = *reinterpret_cast<unsigned*>(&lv);
}

__device__ __forceinline__ void mma16bf(float* d, const unsigned* a, const unsigned* b) {
    asm volatile(
        "mma.sync.aligned.m16n8k16.row.col.f32.bf16.bf16.f32 "
        "{%0,%1,%2,%3}, {%4,%5,%6,%7}, {%8,%9}, {%0,%1,%2,%3};\n"
        : "+f"(d[0]), "+f"(d[1]), "+f"(d[2]), "+f"(d[3])
        : "r"(a[0]), "r"(a[1]), "r"(a[2]), "r"(a[3]), "r"(b[0]), "r"(b[1]));
}

__device__ __forceinline__ void mma16f(float* d, const unsigned* a, const unsigned* b) {
    asm volatile(
        "mma.sync.aligned.m16n8k16.row.col.f32.f16.f16.f32 "
        "{%0,%1,%2,%3}, {%4,%5,%6,%7}, {%8,%9}, {%0,%1,%2,%3};\n"
        : "+f"(d[0]), "+f"(d[1]), "+f"(d[2]), "+f"(d[3])
        : "r"(a[0]), "r"(a[1]), "r"(a[2]), "r"(a[3]), "r"(b[0]), "r"(b[1]));
}

__device__ __forceinline__ uint4 pack8h(float o0, float o1, float o2, float o3,
                                        float o4, float o5, float o6, float o7) {
    __half2 h[4];
    h[0] = __floats2half2_rn(o0, o1);
    h[1] = __floats2half2_rn(o2, o3);
    h[2] = __floats2half2_rn(o4, o5);
    h[3] = __floats2half2_rn(o6, o7);
    return *reinterpret_cast<uint4*>(h);
}

__device__ __forceinline__ void st_m2(int r, int c, float2 v) {
    if (c < C1) {
        *reinterpret_cast<__half2*>(g_XW1H + (size_t)r * C1 + c) =
            __floats2half2_rn(v.x, v.y);
    } else {
        int sc = c - C1;
        if (sc < NH) {
            g_S1S[r * NH + sc]     = v.x;
            g_S1S[r * NH + sc + 1] = v.y;
        } else if (sc < 20) {
            g_S1D[r * NH + sc - NH]     = v.x;
            g_S1D[r * NH + sc - NH + 1] = v.y;
        }
    }
}

// ---------------- GEMM1: bf16x3 (A fp32 feats, K=32) -------------------------
__global__ __launch_bounds__(256)
void k_tgemm1(const float* __restrict__ A, const float* __restrict__ B,
              int M, int N, int K) {
    __shared__ float As[16][136];
    __shared__ float Bs[16][136];
    const int tid  = threadIdx.x;
    const int lane = tid & 31;
    const int wid  = tid >> 5;
    const int qr   = lane >> 2;
    const int qc   = lane & 3;
    const int wm   = (wid & 3) * 32;
    const int wn   = (wid >> 2) * 64;
    const int row0 = blockIdx.x * 128;
    const int col0 = blockIdx.y * 128;

    float acc[2][8][4];
#pragma unroll
    for (int mf = 0; mf < 2; mf++)
#pragma unroll
        for (int nf = 0; nf < 8; nf++)
#pragma unroll
            for (int i = 0; i < 4; i++) acc[mf][nf][i] = 0.f;

    for (int k0 = 0; k0 < K; k0 += 16) {
#pragma unroll
        for (int i = 0; i < 2; i++) {
            int f = tid + i * 256;
            int r = f >> 2, c4 = (f & 3) * 4;
            float4 v = {0.f, 0.f, 0.f, 0.f};
            if (row0 + r < M)
                v = *reinterpret_cast<const float4*>(A + (size_t)(row0 + r) * K + k0 + c4);
            As[c4 + 0][r] = v.x; As[c4 + 1][r] = v.y;
            As[c4 + 2][r] = v.z; As[c4 + 3][r] = v.w;
        }
#pragma unroll
        for (int i = 0; i < 2; i++) {
            int f = tid + i * 256;
            int kk = f >> 5, c4 = (f & 31) * 4;
            float4 v = {0.f, 0.f, 0.f, 0.f};
            const float* src = B + (size_t)(k0 + kk) * N + col0 + c4;
            if (col0 + c4 + 3 < N) {
                v = *reinterpret_cast<const float4*>(src);
            } else {
                if (col0 + c4 + 0 < N) v.x = src[0];
                if (col0 + c4 + 1 < N) v.y = src[1];
                if (col0 + c4 + 2 < N) v.z = src[2];
                if (col0 + c4 + 3 < N) v.w = src[3];
            }
            *reinterpret_cast<float4*>(&Bs[kk][c4]) = v;
        }
        __syncthreads();

        unsigned ah[2][4], al[2][4], bh[8][2], bl[8][2];
#pragma unroll
        for (int mf = 0; mf < 2; mf++) {
            int mb = wm + mf * 16 + qr;
            bfsplit2(As[2*qc][mb],     As[2*qc+1][mb],     ah[mf][0], al[mf][0]);
            bfsplit2(As[2*qc][mb+8],   As[2*qc+1][mb+8],   ah[mf][1], al[mf][1]);
            bfsplit2(As[2*qc+8][mb],   As[2*qc+9][mb],     ah[mf][2], al[mf][2]);
            bfsplit2(As[2*qc+8][mb+8], As[2*qc+9][mb+8],   ah[mf][3], al[mf][3]);
        }
#pragma unroll
        for (int nf = 0; nf < 8; nf++) {
            int nb = wn + nf * 8 + qr;
            bfsplit2(Bs[2*qc][nb],   Bs[2*qc+1][nb], bh[nf][0], bl[nf][0]);
            bfsplit2(Bs[2*qc+8][nb], Bs[2*qc+9][nb], bh[nf][1], bl[nf][1]);
        }
#pragma unroll
        for (int mf = 0; mf < 2; mf++)
#pragma unroll
            for (int nf = 0; nf < 8; nf++) {
                mma16bf(acc[mf][nf], ah[mf], bh[nf]);
                mma16bf(acc[mf][nf], al[mf], bh[nf]);
                mma16bf(acc[mf][nf], ah[mf], bl[nf]);
            }
        __syncthreads();
    }

#pragma unroll
    for (int mf = 0; mf < 2; mf++) {
        int r0 = row0 + wm + mf * 16 + qr;
#pragma unroll
        for (int nf = 0; nf < 8; nf++) {
            int c = col0 + wn + nf * 8 + 2 * qc;
            if (r0 < M)     st_m2(r0, c, make_float2(acc[mf][nf][0], acc[mf][nf][1]));
            if (r0 + 8 < M) st_m2(r0 + 8, c, make_float2(acc[mf][nf][2], acc[mf][nf][3]));
        }
    }
}

// ---------------- fp16 2-term GEMM ------------------------------------------
template <int MODE, typename AT>
__global__ __launch_bounds__(256)
void k_hgemm(const AT* __restrict__ A, const __half* __restrict__ BhT,
             const __half* __restrict__ BlT, const float* __restrict__ bias,
             float* __restrict__ C, int M, int K) {
    __shared__ __half As [128][24];
    __shared__ __half Bhs[128][24];
    __shared__ __half Bls[128][24];
    const int tid  = threadIdx.x;
    const int lane = tid & 31;
    const int wid  = tid >> 5;
    const int qr   = lane >> 2;
    const int qc   = lane & 3;
    const int wm   = (wid & 3) * 32;
    const int wn   = (wid >> 2) * 64;
    const int row0 = blockIdx.x * 128;

    float acc[2][8][4];
#pragma unroll
    for (int mf = 0; mf < 2; mf++)
#pragma unroll
        for (int nf = 0; nf < 8; nf++)
#pragma unroll
            for (int i = 0; i < 4; i++) acc[mf][nf][i] = 0.f;

    const int r  = tid >> 1;
    const int c8 = (tid & 1) * 8;

    for (int k0 = 0; k0 < K; k0 += 16) {
        if (sizeof(AT) == 2) {
            uint4 v = {0u, 0u, 0u, 0u};
            if (row0 + r < M)
                v = *reinterpret_cast<const uint4*>(
                        reinterpret_cast<const __half*>(A) + (size_t)(row0 + r) * K + k0 + c8);
            *reinterpret_cast<uint4*>(&As[r][c8]) = v;
        } else {
            float4 v0 = {0,0,0,0}, v1 = {0,0,0,0};
            if (row0 + r < M) {
                const float* src = reinterpret_cast<const float*>(A) + (size_t)(row0 + r) * K + k0 + c8;
                v0 = *reinterpret_cast<const float4*>(src);
                v1 = *reinterpret_cast<const float4*>(src + 4);
            }
            *reinterpret_cast<__half2*>(&As[r][c8 + 0]) = __floats2half2_rn(v0.x, v0.y);
            *reinterpret_cast<__half2*>(&As[r][c8 + 2]) = __floats2half2_rn(v0.z, v0.w);
            *reinterpret_cast<__half2*>(&As[r][c8 + 4]) = __floats2half2_rn(v1.x, v1.y);
            *reinterpret_cast<__half2*>(&As[r][c8 + 6]) = __floats2half2_rn(v1.z, v1.w);
        }
        {
            uint4 vh = *reinterpret_cast<const uint4*>(BhT + (size_t)r * K + k0 + c8);
            uint4 vl = *reinterpret_cast<const uint4*>(BlT + (size_t)r * K + k0 + c8);
            *reinterpret_cast<uint4*>(&Bhs[r][c8]) = vh;
            *reinterpret_cast<uint4*>(&Bls[r][c8]) = vl;
        }
        __syncthreads();

        unsigned a[2][4], bh[8][2], bl[8][2];
#pragma unroll
        for (int mf = 0; mf < 2; mf++) {
            int mb = wm + mf * 16 + qr;
            a[mf][0] = *reinterpret_cast<const unsigned*>(&As[mb][2 * qc]);
            a[mf][1] = *reinterpret_cast<const unsigned*>(&As[mb + 8][2 * qc]);
            a[mf][2] = *reinterpret_cast<const unsigned*>(&As[mb][2 * qc + 8]);
            a[mf][3] = *reinterpret_cast<const unsigned*>(&As[mb + 8][2 * qc + 8]);
        }
#pragma unroll
        for (int nf = 0; nf < 8; nf++) {
            int nb = wn + nf * 8 + qr;
            bh[nf][0] = *reinterpret_cast<const unsigned*>(&Bhs[nb][2 * qc]);
            bh[nf][1] = *reinterpret_cast<const unsigned*>(&Bhs[nb][2 * qc + 8]);
            bl[nf][0] = *reinterpret_cast<const unsigned*>(&Bls[nb][2 * qc]);
            bl[nf][1] = *reinterpret_cast<const unsigned*>(&Bls[nb][2 * qc + 8]);
        }
#pragma unroll
        for (int mf = 0; mf < 2; mf++)
#pragma unroll
            for (int nf = 0; nf < 8; nf++) {
                mma16f(acc[mf][nf], a[mf], bh[nf]);
                mma16f(acc[mf][nf], a[mf], bl[nf]);
            }
        __syncthreads();
    }

#pragma unroll
    for (int mf = 0; mf < 2; mf++) {
        int r0 = row0 + wm + mf * 16 + qr;
#pragma unroll
        for (int nf = 0; nf < 8; nf++) {
            int c = wn + nf * 8 + 2 * qc;
            float2 v0 = {acc[mf][nf][0], acc[mf][nf][1]};
            float2 v1 = {acc[mf][nf][2], acc[mf][nf][3]};
            if (MODE == 1) {
                float bc0 = bias[c], bc1 = bias[c + 1];
                v0.x = fmaxf(v0.x + bc0, 0.f); v0.y = fmaxf(v0.y + bc1, 0.f);
                v1.x = fmaxf(v1.x + bc0, 0.f); v1.y = fmaxf(v1.y + bc1, 0.f);
                if (r0 < M)
                    *reinterpret_cast<float2*>(C + (size_t)r0 * DOUT + c) = v0;
                if (r0 + 8 < M)
                    *reinterpret_cast<float2*>(C + (size_t)(r0 + 8) * DOUT + c) = v1;
            } else {
                if (r0 < M)
                    *reinterpret_cast<__half2*>(g_XW2H + (size_t)r0 * DOUT + c) =
                        __floats2half2_rn(v0.x, v0.y);
                if (r0 + 8 < M)
                    *reinterpret_cast<__half2*>(g_XW2H + (size_t)(r0 + 8) * DOUT + c) =
                        __floats2half2_rn(v1.x, v1.y);
            }
        }
    }
}

// ---------------- merged prep: edge count + B1E + W2/fcw split + Q2 ----------
#define CNT_BLKS  910
#define BEXT_BLKS 32
#define PREP_W2   (C1 * DOUT)
#define PREP_FC   (PREP_W2 + DOUT * DOUT)
#define PREP_TOT  (PREP_FC + C1 * 32)
#define PREP_BLKS (PREP_TOT / 352)
#define PRE_BLKS  (CNT_BLKS + BEXT_BLKS + PREP_BLKS)

__global__ __launch_bounds__(352)
void k_pre(const int* __restrict__ edst, const float* __restrict__ W1,
           const float* __restrict__ a1s, const float* __restrict__ a1d,
           const float* __restrict__ W2, const float* __restrict__ fcw,
           const float* __restrict__ a2s, const float* __restrict__ a2d) {
    int b = blockIdx.x, t = threadIdx.x;
    if (b < CNT_BLKS) {
        int e = b * 352 + t;
        if (e < EE) atomicAdd(&g_DEG[edst[e]], 1);
    } else if (b < CNT_BLKS + BEXT_BLKS) {
        int k = b - CNT_BLKS;
        int j = t;
        if (j >= C1E) return;
        float v;
        if (j < C1) {
            v = W1[k * C1 + j];
        } else if (j < C1 + NH) {
            int h = j - C1;
            float s = 0.f;
            for (int f = 0; f < FIN; f++)
                s += W1[k * C1 + h * FIN + f] * a1s[h * FIN + f];
            v = s;
        } else {
            int h = j - C1 - NH;
            float s = 0.f;
            for (int f = 0; f < FIN; f++)
                s += W1[k * C1 + h * FIN + f] * a1d[h * FIN + f];
            v = s;
        }
        g_B1E[k * C1E + j] = v;
    } else {
        int gid = (b - CNT_BLKS - BEXT_BLKS) * 352 + t;
        if (gid < PREP_W2) {
            int k = gid / DOUT, n = gid % DOUT;
            float w = W2[gid];
            __half h = __float2half_rn(w);
            g_W2H[n * C1 + k] = h;
            g_W2L[n * C1 + k] = __float2half_rn(w - __half2float(h));
        } else if (gid < PREP_FC) {
            int e = gid - PREP_W2;
            int k = e / DOUT, n = e % DOUT;
            float w = fcw[e];
            __half h = __float2half_rn(w);
            g_FWH[n * DOUT + k] = h;
            g_FWL[n * DOUT + k] = __float2half_rn(w - __half2float(h));
        } else {
            int t2 = gid - PREP_FC;
            int k = t2 >> 5, lane = t2 & 31;
            if (k >= C1) return;
            float s = 0.f, d = 0.f;
#pragma unroll
            for (int j = 0; j < 4; j++) {
                float w = W2[k * DOUT + j * 32 + lane];
                s += w * a2s[j * 32 + lane];
                d += w * a2d[j * 32 + lane];
            }
#pragma unroll
            for (int o = 16; o > 0; o >>= 1) {
                s += __shfl_down_sync(0xffffffffu, s, o);
                d += __shfl_down_sync(0xffffffffu, d, o);
            }
            if (lane == 0) { g_Q2S[k] = s; g_Q2D[k] = d; }
        }
    }
}

// ---------------- scan: warp-shuffle hierarchy + decoupled lookback -----------
__global__ void k_scan() {
    __shared__ int swarp[32];
    __shared__ int s_boff;
    int* flags = g_DEG + NN;
    int b = blockIdx.x, t = threadIdx.x;
    int wid = t >> 5, lane = t & 31;
    int n = b * 1024 + t;
    int v = (n < NN) ? g_DEG[n] + 1 : 0;

    // warp inclusive scan
    int x = v;
#pragma unroll
    for (int o = 1; o < 32; o <<= 1) {
        int u = __shfl_up_sync(0xffffffffu, x, o);
        if (lane >= o) x += u;
    }
    if (lane == 31) swarp[wid] = x;
    __syncthreads();
    if (wid == 0) {
        int y = swarp[lane];
#pragma unroll
        for (int o = 1; o < 32; o <<= 1) {
            int u = __shfl_up_sync(0xffffffffu, y, o);
            if (lane >= o) y += u;
        }
        swarp[lane] = y;
    }
    __syncthreads();
    int incl = x + (wid > 0 ? swarp[wid - 1] : 0);   // block-inclusive

    if (t == 1023) {
        g_BSUM[b] = incl;                            // block total
        __threadfence();
        atomicExch(&flags[b], 1);
    }
    if (t < 32) {
        int p = 0;
        if (t < b) {
            while (atomicAdd(&flags[t], 0) == 0) {}
            p = g_BSUM[t];
        }
#pragma unroll
        for (int o = 16; o > 0; o >>= 1)
            p += __shfl_down_sync(0xffffffffu, p, o);
        if (t == 0) s_boff = p;
    }
    __syncthreads();
    if (n < NN) {
        int r = incl - v + s_boff;
        g_ROWPTR[n] = r;
        g_ROWCUR[n] = r;
    }
    if (b == 19 && t == 1023) g_ROWPTR[NN] = ETOT;
    if (n < BG * DOUT) g_X2E[(size_t)NN * DOUT + n] = 0.f;
}

__global__ void k_scatter(const int* __restrict__ esrc, const int* __restrict__ edst) {
    int e = blockIdx.x * blockDim.x + threadIdx.x;
    if (e >= ETOT) return;
    int s, d;
    if (e < EE) { s = esrc[e]; d = edst[e]; } else { s = d = e - EE; }
    int pos = atomicAdd(&g_ROWCUR[d], 1);
    g_ESRT[pos] = s;
}

// ---------------- layer-1 aggregation: 2 edges/iter, uint4 gather -------------
__global__ __launch_bounds__(256)
void k_agg1(const float* __restrict__ b1) {
    int lane = threadIdx.x & 31;
    int n = (blockIdx.x * blockDim.x + threadIdx.x) >> 5;
    if (n >= NN) return;
    int p0 = g_ROWPTR[n], p1 = g_ROWPTR[n + 1];
    float sd = (lane < NH) ? g_S1D[n * NH + lane] : 0.f;
    const int hA = lane >> 2;
    const int hB = 8 + (lane >> 2);
    bool sact = (lane < NH);

    float2 accA[4], accB[4];
#pragma unroll
    for (int j = 0; j < 4; j++) { accA[j] = make_float2(0.f, 0.f); accB[j] = make_float2(0.f, 0.f); }
    float denom = 0.f;

    for (int k = p0; k < p1; k += 2) {
        bool has1 = (k + 1 < p1);
        int s0 = g_ESRT[k];
        int s1 = g_ESRT[has1 ? k + 1 : k];
        float sc0 = sact ? g_S1S[s0 * NH + lane] : 0.f;
        float sc1 = sact ? g_S1S[s1 * NH + lane] : 0.f;
        float ex0 = sact ? __expf(leakyf(sc0 + sd)) : 0.f;
        float ex1 = (sact && has1) ? __expf(leakyf(sc1 + sd)) : 0.f;
        denom += ex0 + ex1;
        const uint4* r0 = reinterpret_cast<const uint4*>(g_XW1H + (size_t)s0 * C1);
        const uint4* r1 = reinterpret_cast<const uint4*>(g_XW1H + (size_t)s1 * C1);
        uint4 va0 = r0[lane];
        uint4 va1 = r1[lane];
        float aA0 = __shfl_sync(0xffffffffu, ex0, hA);
        float aA1 = __shfl_sync(0xffffffffu, ex1, hA);
        float aB0 = __shfl_sync(0xffffffffu, ex0, hB);
        float aB1 = __shfl_sync(0xffffffffu, ex1, hB);
        const __half2* h0 = reinterpret_cast<const __half2*>(&va0);
        const __half2* h1 = reinterpret_cast<const __half2*>(&va1);
#pragma unroll
        for (int j = 0; j < 4; j++) {
            float2 f0 = __half22float2(h0[j]);
            float2 f1 = __half22float2(h1[j]);
            accA[j].x = fmaf(aA0, f0.x, fmaf(aA1, f1.x, accA[j].x));
            accA[j].y = fmaf(aA0, f0.y, fmaf(aA1, f1.y, accA[j].y));
        }
        if (lane < 8) {
            uint4 vb0 = r0[32 + lane];
            uint4 vb1 = r1[32 + lane];
            const __half2* g0 = reinterpret_cast<const __half2*>(&vb0);
            const __half2* g1 = reinterpret_cast<const __half2*>(&vb1);
#pragma unroll
            for (int j = 0; j < 4; j++) {
                float2 f0 = __half22float2(g0[j]);
                float2 f1 = __half22float2(g1[j]);
                accB[j].x = fmaf(aB0, f0.x, fmaf(aB1, f1.x, accB[j].x));
                accB[j].y = fmaf(aB0, f0.y, fmaf(aB1, f1.y, accB[j].y));
            }
        }
    }

    float dA = fmaxf(__shfl_sync(0xffffffffu, denom, hA), 1e-16f);
    float dB = fmaxf(__shfl_sync(0xffffffffu, denom, hB), 1e-16f);

    float vs = 0.f, vd = 0.f;
    {
        int c0 = 8 * lane;
        float4 bb0 = *reinterpret_cast<const float4*>(b1 + c0);
        float4 bb1 = *reinterpret_cast<const float4*>(b1 + c0 + 4);
        float o0 = eluf(accA[0].x / dA + bb0.x);
        float o1 = eluf(accA[0].y / dA + bb0.y);
        float o2 = eluf(accA[1].x / dA + bb0.z);
        float o3 = eluf(accA[1].y / dA + bb0.w);
        float o4 = eluf(accA[2].x / dA + bb1.x);
        float o5 = eluf(accA[2].y / dA + bb1.y);
        float o6 = eluf(accA[3].x / dA + bb1.z);
        float o7 = eluf(accA[3].y / dA + bb1.w);
        *reinterpret_cast<uint4*>(g_X1H + (size_t)n * C1 + c0) =
            pack8h(o0, o1, o2, o3, o4, o5, o6, o7);
        float4 q0 = *reinterpret_cast<const float4*>(g_Q2S + c0);
        float4 q1 = *reinterpret_cast<const float4*>(g_Q2S + c0 + 4);
        float4 r0 = *reinterpret_cast<const float4*>(g_Q2D + c0);
        float4 r1 = *reinterpret_cast<const float4*>(g_Q2D + c0 + 4);
        vs += o0*q0.x + o1*q0.y + o2*q0.z + o3*q0.w + o4*q1.x + o5*q1.y + o6*q1.z + o7*q1.w;
        vd += o0*r0.x + o1*r0.y + o2*r0.z + o3*r0.w + o4*r1.x + o5*r1.y + o6*r1.z + o7*r1.w;
    }
    if (lane < 8) {
        int c0 = 256 + 8 * lane;
        float4 bb0 = *reinterpret_cast<const float4*>(b1 + c0);
        float4 bb1 = *reinterpret_cast<const float4*>(b1 + c0 + 4);
        float o0 = eluf(accB[0].x / dB + bb0.x);
        float o1 = eluf(accB[0].y / dB + bb0.y);
        float o2 = eluf(accB[1].x / dB + bb0.z);
        float o3 = eluf(accB[1].y / dB + bb0.w);
        float o4 = eluf(accB[2].x / dB + bb1.x);
        float o5 = eluf(accB[2].y / dB + bb1.y);
        float o6 = eluf(accB[3].x / dB + bb1.z);
        float o7 = eluf(accB[3].y / dB + bb1.w);
        *reinterpret_cast<uint4*>(g_X1H + (size_t)n * C1 + c0) =
            pack8h(o0, o1, o2, o3, o4, o5, o6, o7);
        float4 q0 = *reinterpret_cast<const float4*>(g_Q2S + c0);
        float4 q1 = *reinterpret_cast<const float4*>(g_Q2S + c0 + 4);
        float4 r0 = *reinterpret_cast<const float4*>(g_Q2D + c0);
        float4 r1 = *reinterpret_cast<const float4*>(g_Q2D + c0 + 4);
        vs += o0*q0.x + o1*q0.y + o2*q0.z + o3*q0.w + o4*q1.x + o5*q1.y + o6*q1.z + o7*q1.w;
        vd += o0*r0.x + o1*r0.y + o2*r0.z + o3*r0.w + o4*r1.x + o5*r1.y + o6*r1.z + o7*r1.w;
    }
#pragma unroll
    for (int o = 16; o > 0; o >>= 1) {
        vs += __shfl_down_sync(0xffffffffu, vs, o);
        vd += __shfl_down_sync(0xffffffffu, vd, o);
    }
    if (lane == 0) { g_S2S[n] = vs; g_S2D[n] = vd; }
}

// ---------------- layer-2 aggregation: 4 edges/iter + smem-staged pool --------
__global__ __launch_bounds__(256)
void k_agg2(const float* __restrict__ b2) {
    __shared__ int smax[DOUT];
    int tid = threadIdx.x;
    int lane = tid & 31;
    int n = (blockIdx.x * blockDim.x + tid) >> 5;
    if (tid < DOUT) smax[tid] = 0;
    __syncthreads();

    if (n < NN) {
        int p0 = g_ROWPTR[n], p1 = g_ROWPTR[n + 1];
        float sd = g_S2D[n];
        int half = lane >> 4, li = lane & 15;

        float2 acc[4];
#pragma unroll
        for (int j = 0; j < 4; j++) acc[j] = make_float2(0.f, 0.f);
        float denom = 0.f;

        for (int k = p0; k < p1; k += 4) {
            int kk0 = k + half;
            int kk1 = k + 2 + half;
            int kc0 = (kk0 < p1) ? kk0 : p1 - 1;
            int kc1 = (kk1 < p1) ? kk1 : p1 - 1;
            int s0 = g_ESRT[kc0];
            int s1 = g_ESRT[kc1];
            float sc0 = g_S2S[s0];
            float sc1 = g_S2S[s1];
            float ex0 = (kk0 < p1) ? __expf(leakyf(sc0 + sd)) : 0.f;
            float ex1 = (kk1 < p1) ? __expf(leakyf(sc1 + sd)) : 0.f;
            denom += ex0 + ex1;
            uint4 v0 = reinterpret_cast<const uint4*>(g_XW2H + (size_t)s0 * DOUT)[li];
            uint4 v1 = reinterpret_cast<const uint4*>(g_XW2H + (size_t)s1 * DOUT)[li];
            const __half2* h0 = reinterpret_cast<const __half2*>(&v0);
            const __half2* h1 = reinterpret_cast<const __half2*>(&v1);
#pragma unroll
            for (int j = 0; j < 4; j++) {
                float2 f0 = __half22float2(h0[j]);
                float2 f1 = __half22float2(h1[j]);
                acc[j].x = fmaf(ex0, f0.x, fmaf(ex1, f1.x, acc[j].x));
                acc[j].y = fmaf(ex0, f0.y, fmaf(ex1, f1.y, acc[j].y));
            }
        }
        denom += __shfl_xor_sync(0xffffffffu, denom, 16);
#pragma unroll
        for (int j = 0; j < 4; j++) {
            acc[j].x += __shfl_xor_sync(0xffffffffu, acc[j].x, 16);
            acc[j].y += __shfl_xor_sync(0xffffffffu, acc[j].y, 16);
        }
        float dn = fmaxf(denom, 1e-16f);

        if (half == 0) {
            int c0 = 8 * li;
            float4 bb0 = *reinterpret_cast<const float4*>(b2 + c0);
            float4 bb1 = *reinterpret_cast<const float4*>(b2 + c0 + 4);
            float4 w0, w1;
            w0.x = fmaxf(acc[0].x / dn + bb0.x, 0.f);
            w0.y = fmaxf(acc[0].y / dn + bb0.y, 0.f);
            w0.z = fmaxf(acc[1].x / dn + bb0.z, 0.f);
            w0.w = fmaxf(acc[1].y / dn + bb0.w, 0.f);
            w1.x = fmaxf(acc[2].x / dn + bb1.x, 0.f);
            w1.y = fmaxf(acc[2].y / dn + bb1.y, 0.f);
            w1.z = fmaxf(acc[3].x / dn + bb1.z, 0.f);
            w1.w = fmaxf(acc[3].y / dn + bb1.w, 0.f);
            *reinterpret_cast<float4*>(g_X2E + (size_t)n * DOUT + c0)     = w0;
            *reinterpret_cast<float4*>(g_X2E + (size_t)n * DOUT + c0 + 4) = w1;
            atomicMax(&smax[c0 + 0], __float_as_int(w0.x));
            atomicMax(&smax[c0 + 1], __float_as_int(w0.y));
            atomicMax(&smax[c0 + 2], __float_as_int(w0.z));
            atomicMax(&smax[c0 + 3], __float_as_int(w0.w));
            atomicMax(&smax[c0 + 4], __float_as_int(w1.x));
            atomicMax(&smax[c0 + 5], __float_as_int(w1.y));
            atomicMax(&smax[c0 + 6], __float_as_int(w1.z));
            atomicMax(&smax[c0 + 7], __float_as_int(w1.w));
        }
    }
    __syncthreads();
    if (tid < DOUT) {
        int grow = NN + (blockIdx.x * 8) / PERN;
        atomicMax(reinterpret_cast<int*>(g_X2E + (size_t)grow * DOUT) + tid, smax[tid]);
    }
}

// ============================================================================
extern "C" void kernel_launch(void* const* d_in, const int* in_sizes, int n_in,
                              void* d_out, int out_size) {
    const float* feats = (const float*)d_in[0];
    const int*   ei    = (const int*)d_in[1];
    const int*   esrc  = ei;
    const int*   edst  = ei + EE;
    const float* W1  = (const float*)d_in[4];
    const float* a1s = (const float*)d_in[5];
    const float* a1d = (const float*)d_in[6];
    const float* b1  = (const float*)d_in[7];
    const float* W2  = (const float*)d_in[8];
    const float* a2s = (const float*)d_in[9];
    const float* a2d = (const float*)d_in[10];
    const float* b2  = (const float*)d_in[11];
    const float* fcw = (const float*)d_in[12];
    const float* fcb = (const float*)d_in[13];
    float* out = (float*)d_out;

    void *pX1H, *pX2E, *pB1E, *pDEG, *pW2H, *pW2L, *pFWH, *pFWL;
    cudaGetSymbolAddress(&pX1H, g_X1H);
    cudaGetSymbolAddress(&pX2E, g_X2E);
    cudaGetSymbolAddress(&pB1E, g_B1E);
    cudaGetSymbolAddress(&pDEG, g_DEG);
    cudaGetSymbolAddress(&pW2H, g_W2H);
    cudaGetSymbolAddress(&pW2L, g_W2L);
    cudaGetSymbolAddress(&pFWH, g_FWH);
    cudaGetSymbolAddress(&pFWL, g_FWL);

    static cudaStream_t s2 = nullptr;
    static cudaEvent_t evF = nullptr, evJ = nullptr;
    if (!s2) {
        cudaStreamCreateWithFlags(&s2, cudaStreamNonBlocking);
        cudaEventCreateWithFlags(&evF, cudaEventDisableTiming);
        cudaEventCreateWithFlags(&evJ, cudaEventDisableTiming);
    }

    const int WB = 256;
    int warpBlocks = (NN * 32 + WB - 1) / WB;

    cudaMemsetAsync(pDEG, 0, (NN + 32) * sizeof(int));

    k_pre<<<PRE_BLKS, 352>>>(edst, W1, a1s, a1d, W2, fcw, a2s, a2d);

    cudaEventRecord(evF, 0);
    cudaStreamWaitEvent(s2, evF, 0);

    dim3 g1((NN + 127) / 128, (C1E + 127) / 128);
    k_tgemm1<<<g1, 256, 0, s2>>>(feats, (const float*)pB1E, NN, C1E, FIN);

    k_scan<<<20, 1024>>>();
    k_scatter<<<(ETOT + 255) / 256, 256>>>(esrc, edst);

    cudaEventRecord(evJ, s2);
    cudaStreamWaitEvent(0, evJ, 0);

    k_agg1<<<warpBlocks, WB>>>(b1);

    k_hgemm<4, __half><<<(NN + 127) / 128, 256>>>(
        (const __half*)pX1H, (const __half*)pW2H, (const __half*)pW2L,
        nullptr, nullptr, NN, C1);

    k_agg2<<<warpBlocks, WB>>>(b2);

    k_hgemm<1, float><<<(NN + BG + 127) / 128, 256>>>(
        (const float*)pX2E, (const __half*)pFWH, (const __half*)pFWL,
        fcb, out, NN + BG, DOUT);
}

// round 16
// speedup vs baseline: 1.0462x; 1.0462x over previous
#include <cuda_runtime.h>
#include <cuda_fp16.h>
#include <cuda_bf16.h>

#define NN    20000
#define BG    100
#define PERN  200
#define EE    320000
#define ETOT  340000
#define FIN   32
#define NH    10
#define C1    320
#define C1E   340
#define DOUT  128
#define NEG_SLOPE 0.2f

// ---------------- scratch ----------------------------------------------------
__device__ __half g_XW1H[NN * C1];
__device__ float  g_S1S [NN * NH];
__device__ float  g_S1D [NN * NH];
__device__ __half g_X1H [NN * C1];
__device__ __half g_XW2H[NN * DOUT];
__device__ float  g_S2S [NN];
__device__ float  g_S2D [NN];
__device__ float  g_X2E [(NN + BG) * DOUT];
__device__ float  g_B1E [FIN * C1E];
__device__ float  g_Q2S [C1];
__device__ float  g_Q2D [C1];
__device__ __half g_W2H [DOUT * C1];
__device__ __half g_W2L [DOUT * C1];
__device__ __half g_FWH [DOUT * DOUT];
__device__ __half g_FWL [DOUT * DOUT];
__device__ int    g_DEG[NN + 32];           // [NN..NN+20) = lookback flags
__device__ int    g_ROWPTR[NN + 1];
__device__ int    g_ROWCUR[NN];
__device__ int    g_ESRT[ETOT];
__device__ int    g_BSUM[32];

__device__ __forceinline__ float leakyf(float x) { return x > 0.f ? x : NEG_SLOPE * x; }
__device__ __forceinline__ float eluf(float x)   { return x > 0.f ? x : __expf(x) - 1.f; }

__device__ __forceinline__ void bfsplit2(float x0, float x1, unsigned& h, unsigned& l) {
    __nv_bfloat162 hv = __floats2bfloat162_rn(x0, x1);
    float r0 = x0 - __bfloat162float(hv.x);
    float r1 = x1 - __bfloat162float(hv.y);
    __nv_bfloat162 lv = __floats2bfloat162_rn(r0, r1);
    h = *reinterpret_cast<unsigned*>(&hv);
    l = *reinterpret_cast<unsigned*>(&lv);
}

__device__ __forceinline__ void mma16bf(float* d, const unsigned* a, const unsigned* b) {
    asm volatile(
        "mma.sync.aligned.m16n8k16.row.col.f32.bf16.bf16.f32 "
        "{%0,%1,%2,%3}, {%4,%5,%6,%7}, {%8,%9}, {%0,%1,%2,%3};\n"
        : "+f"(d[0]), "+f"(d[1]), "+f"(d[2]), "+f"(d[3])
        : "r"(a[0]), "r"(a[1]), "r"(a[2]), "r"(a[3]), "r"(b[0]), "r"(b[1]));
}

__device__ __forceinline__ void mma16f(float* d, const unsigned* a, const unsigned* b) {
    asm volatile(
        "mma.sync.aligned.m16n8k16.row.col.f32.f16.f16.f32 "
        "{%0,%1,%2,%3}, {%4,%5,%6,%7}, {%8,%9}, {%0,%1,%2,%3};\n"
        : "+f"(d[0]), "+f"(d[1]), "+f"(d[2]), "+f"(d[3])
        : "r"(a[0]), "r"(a[1]), "r"(a[2]), "r"(a[3]), "r"(b[0]), "r"(b[1]));
}

__device__ __forceinline__ uint4 pack8h(float o0, float o1, float o2, float o3,
                                        float o4, float o5, float o6, float o7) {
    __half2 h[4];
    h[0] = __floats2half2_rn(o0, o1);
    h[1] = __floats2half2_rn(o2, o3);
    h[2] = __floats2half2_rn(o4, o5);
    h[3] = __floats2half2_rn(o6, o7);
    return *reinterpret_cast<uint4*>(h);
}

__device__ __forceinline__ void st_m2(int r, int c, float2 v) {
    if (c < C1) {
        *reinterpret_cast<__half2*>(g_XW1H + (size_t)r * C1 + c) =
            __floats2half2_rn(v.x, v.y);
    } else {
        int sc = c - C1;
        if (sc < NH) {
            g_S1S[r * NH + sc]     = v.x;
            g_S1S[r * NH + sc + 1] = v.y;
        } else if (sc < 20) {
            g_S1D[r * NH + sc - NH]     = v.x;
            g_S1D[r * NH + sc - NH + 1] = v.y;
        }
    }
}

// ---------------- GEMM1: bf16x3 (A fp32 feats, K=32) -------------------------
__global__ __launch_bounds__(256)
void k_tgemm1(const float* __restrict__ A, const float* __restrict__ B,
              int M, int N, int K) {
    __shared__ float As[16][136];
    __shared__ float Bs[16][136];
    const int tid  = threadIdx.x;
    const int lane = tid & 31;
    const int wid  = tid >> 5;
    const int qr   = lane >> 2;
    const int qc   = lane & 3;
    const int wm   = (wid & 3) * 32;
    const int wn   = (wid >> 2) * 64;
    const int row0 = blockIdx.x * 128;
    const int col0 = blockIdx.y * 128;

    float acc[2][8][4];
#pragma unroll
    for (int mf = 0; mf < 2; mf++)
#pragma unroll
        for (int nf = 0; nf < 8; nf++)
#pragma unroll
            for (int i = 0; i < 4; i++) acc[mf][nf][i] = 0.f;

    for (int k0 = 0; k0 < K; k0 += 16) {
#pragma unroll
        for (int i = 0; i < 2; i++) {
            int f = tid + i * 256;
            int r = f >> 2, c4 = (f & 3) * 4;
            float4 v = {0.f, 0.f, 0.f, 0.f};
            if (row0 + r < M)
                v = *reinterpret_cast<const float4*>(A + (size_t)(row0 + r) * K + k0 + c4);
            As[c4 + 0][r] = v.x; As[c4 + 1][r] = v.y;
            As[c4 + 2][r] = v.z; As[c4 + 3][r] = v.w;
        }
#pragma unroll
        for (int i = 0; i < 2; i++) {
            int f = tid + i * 256;
            int kk = f >> 5, c4 = (f & 31) * 4;
            float4 v = {0.f, 0.f, 0.f, 0.f};
            const float* src = B + (size_t)(k0 + kk) * N + col0 + c4;
            if (col0 + c4 + 3 < N) {
                v = *reinterpret_cast<const float4*>(src);
            } else {
                if (col0 + c4 + 0 < N) v.x = src[0];
                if (col0 + c4 + 1 < N) v.y = src[1];
                if (col0 + c4 + 2 < N) v.z = src[2];
                if (col0 + c4 + 3 < N) v.w = src[3];
            }
            *reinterpret_cast<float4*>(&Bs[kk][c4]) = v;
        }
        __syncthreads();

        unsigned ah[2][4], al[2][4], bh[8][2], bl[8][2];
#pragma unroll
        for (int mf = 0; mf < 2; mf++) {
            int mb = wm + mf * 16 + qr;
            bfsplit2(As[2*qc][mb],     As[2*qc+1][mb],     ah[mf][0], al[mf][0]);
            bfsplit2(As[2*qc][mb+8],   As[2*qc+1][mb+8],   ah[mf][1], al[mf][1]);
            bfsplit2(As[2*qc+8][mb],   As[2*qc+9][mb],     ah[mf][2], al[mf][2]);
            bfsplit2(As[2*qc+8][mb+8], As[2*qc+9][mb+8],   ah[mf][3], al[mf][3]);
        }
#pragma unroll
        for (int nf = 0; nf < 8; nf++) {
            int nb = wn + nf * 8 + qr;
            bfsplit2(Bs[2*qc][nb],   Bs[2*qc+1][nb], bh[nf][0], bl[nf][0]);
            bfsplit2(Bs[2*qc+8][nb], Bs[2*qc+9][nb], bh[nf][1], bl[nf][1]);
        }
#pragma unroll
        for (int mf = 0; mf < 2; mf++)
#pragma unroll
            for (int nf = 0; nf < 8; nf++) {
                mma16bf(acc[mf][nf], ah[mf], bh[nf]);
                mma16bf(acc[mf][nf], al[mf], bh[nf]);
                mma16bf(acc[mf][nf], ah[mf], bl[nf]);
            }
        __syncthreads();
    }

#pragma unroll
    for (int mf = 0; mf < 2; mf++) {
        int r0 = row0 + wm + mf * 16 + qr;
#pragma unroll
        for (int nf = 0; nf < 8; nf++) {
            int c = col0 + wn + nf * 8 + 2 * qc;
            if (r0 < M)     st_m2(r0, c, make_float2(acc[mf][nf][0], acc[mf][nf][1]));
            if (r0 + 8 < M) st_m2(r0 + 8, c, make_float2(acc[mf][nf][2], acc[mf][nf][3]));
        }
    }
}

// ---------------- fp16 2-term GEMM ------------------------------------------
template <int MODE, typename AT>
__global__ __launch_bounds__(256)
void k_hgemm(const AT* __restrict__ A, const __half* __restrict__ BhT,
             const __half* __restrict__ BlT, const float* __restrict__ bias,
             float* __restrict__ C, int M, int K) {
    __shared__ __half As [128][24];
    __shared__ __half Bhs[128][24];
    __shared__ __half Bls[128][24];
    const int tid  = threadIdx.x;
    const int lane = tid & 31;
    const int wid  = tid >> 5;
    const int qr   = lane >> 2;
    const int qc   = lane & 3;
    const int wm   = (wid & 3) * 32;
    const int wn   = (wid >> 2) * 64;
    const int row0 = blockIdx.x * 128;

    float acc[2][8][4];
#pragma unroll
    for (int mf = 0; mf < 2; mf++)
#pragma unroll
        for (int nf = 0; nf < 8; nf++)
#pragma unroll
            for (int i = 0; i < 4; i++) acc[mf][nf][i] = 0.f;

    const int r  = tid >> 1;
    const int c8 = (tid & 1) * 8;

    for (int k0 = 0; k0 < K; k0 += 16) {
        if (sizeof(AT) == 2) {
            uint4 v = {0u, 0u, 0u, 0u};
            if (row0 + r < M)
                v = *reinterpret_cast<const uint4*>(
                        reinterpret_cast<const __half*>(A) + (size_t)(row0 + r) * K + k0 + c8);
            *reinterpret_cast<uint4*>(&As[r][c8]) = v;
        } else {
            float4 v0 = {0,0,0,0}, v1 = {0,0,0,0};
            if (row0 + r < M) {
                const float* src = reinterpret_cast<const float*>(A) + (size_t)(row0 + r) * K + k0 + c8;
                v0 = *reinterpret_cast<const float4*>(src);
                v1 = *reinterpret_cast<const float4*>(src + 4);
            }
            *reinterpret_cast<__half2*>(&As[r][c8 + 0]) = __floats2half2_rn(v0.x, v0.y);
            *reinterpret_cast<__half2*>(&As[r][c8 + 2]) = __floats2half2_rn(v0.z, v0.w);
            *reinterpret_cast<__half2*>(&As[r][c8 + 4]) = __floats2half2_rn(v1.x, v1.y);
            *reinterpret_cast<__half2*>(&As[r][c8 + 6]) = __floats2half2_rn(v1.z, v1.w);
        }
        {
            uint4 vh = *reinterpret_cast<const uint4*>(BhT + (size_t)r * K + k0 + c8);
            uint4 vl = *reinterpret_cast<const uint4*>(BlT + (size_t)r * K + k0 + c8);
            *reinterpret_cast<uint4*>(&Bhs[r][c8]) = vh;
            *reinterpret_cast<uint4*>(&Bls[r][c8]) = vl;
        }
        __syncthreads();

        unsigned a[2][4], bh[8][2], bl[8][2];
#pragma unroll
        for (int mf = 0; mf < 2; mf++) {
            int mb = wm + mf * 16 + qr;
            a[mf][0] = *reinterpret_cast<const unsigned*>(&As[mb][2 * qc]);
            a[mf][1] = *reinterpret_cast<const unsigned*>(&As[mb + 8][2 * qc]);
            a[mf][2] = *reinterpret_cast<const unsigned*>(&As[mb][2 * qc + 8]);
            a[mf][3] = *reinterpret_cast<const unsigned*>(&As[mb + 8][2 * qc + 8]);
        }
#pragma unroll
        for (int nf = 0; nf < 8; nf++) {
            int nb = wn + nf * 8 + qr;
            bh[nf][0] = *reinterpret_cast<const unsigned*>(&Bhs[nb][2 * qc]);
            bh[nf][1] = *reinterpret_cast<const unsigned*>(&Bhs[nb][2 * qc + 8]);
            bl[nf][0] = *reinterpret_cast<const unsigned*>(&Bls[nb][2 * qc]);
            bl[nf][1] = *reinterpret_cast<const unsigned*>(&Bls[nb][2 * qc + 8]);
        }
#pragma unroll
        for (int mf = 0; mf < 2; mf++)
#pragma unroll
            for (int nf = 0; nf < 8; nf++) {
                mma16f(acc[mf][nf], a[mf], bh[nf]);
                mma16f(acc[mf][nf], a[mf], bl[nf]);
            }
        __syncthreads();
    }

#pragma unroll
    for (int mf = 0; mf < 2; mf++) {
        int r0 = row0 + wm + mf * 16 + qr;
#pragma unroll
        for (int nf = 0; nf < 8; nf++) {
            int c = wn + nf * 8 + 2 * qc;
            float2 v0 = {acc[mf][nf][0], acc[mf][nf][1]};
            float2 v1 = {acc[mf][nf][2], acc[mf][nf][3]};
            if (MODE == 1) {
                float bc0 = bias[c], bc1 = bias[c + 1];
                v0.x = fmaxf(v0.x + bc0, 0.f); v0.y = fmaxf(v0.y + bc1, 0.f);
                v1.x = fmaxf(v1.x + bc0, 0.f); v1.y = fmaxf(v1.y + bc1, 0.f);
                if (r0 < M)
                    *reinterpret_cast<float2*>(C + (size_t)r0 * DOUT + c) = v0;
                if (r0 + 8 < M)
                    *reinterpret_cast<float2*>(C + (size_t)(r0 + 8) * DOUT + c) = v1;
            } else {
                if (r0 < M)
                    *reinterpret_cast<__half2*>(g_XW2H + (size_t)r0 * DOUT + c) =
                        __floats2half2_rn(v0.x, v0.y);
                if (r0 + 8 < M)
                    *reinterpret_cast<__half2*>(g_XW2H + (size_t)(r0 + 8) * DOUT + c) =
                        __floats2half2_rn(v1.x, v1.y);
            }
        }
    }
}

// ---------------- merged prep: edge count + B1E + W2/fcw split + Q2 ----------
#define CNT_BLKS  910
#define BEXT_BLKS 32
#define PREP_W2   (C1 * DOUT)
#define PREP_FC   (PREP_W2 + DOUT * DOUT)
#define PREP_TOT  (PREP_FC + C1 * 32)
#define PREP_BLKS (PREP_TOT / 352)
#define PRE_BLKS  (CNT_BLKS + BEXT_BLKS + PREP_BLKS)

__global__ __launch_bounds__(352)
void k_pre(const int* __restrict__ edst, const float* __restrict__ W1,
           const float* __restrict__ a1s, const float* __restrict__ a1d,
           const float* __restrict__ W2, const float* __restrict__ fcw,
           const float* __restrict__ a2s, const float* __restrict__ a2d) {
    int b = blockIdx.x, t = threadIdx.x;
    if (b < CNT_BLKS) {
        int e = b * 352 + t;
        if (e < EE) atomicAdd(&g_DEG[edst[e]], 1);
    } else if (b < CNT_BLKS + BEXT_BLKS) {
        int k = b - CNT_BLKS;
        int j = t;
        if (j >= C1E) return;
        float v;
        if (j < C1) {
            v = W1[k * C1 + j];
        } else if (j < C1 + NH) {
            int h = j - C1;
            float s = 0.f;
            for (int f = 0; f < FIN; f++)
                s += W1[k * C1 + h * FIN + f] * a1s[h * FIN + f];
            v = s;
        } else {
            int h = j - C1 - NH;
            float s = 0.f;
            for (int f = 0; f < FIN; f++)
                s += W1[k * C1 + h * FIN + f] * a1d[h * FIN + f];
            v = s;
        }
        g_B1E[k * C1E + j] = v;
    } else {
        int gid = (b - CNT_BLKS - BEXT_BLKS) * 352 + t;
        if (gid < PREP_W2) {
            int k = gid / DOUT, n = gid % DOUT;
            float w = W2[gid];
            __half h = __float2half_rn(w);
            g_W2H[n * C1 + k] = h;
            g_W2L[n * C1 + k] = __float2half_rn(w - __half2float(h));
        } else if (gid < PREP_FC) {
            int e = gid - PREP_W2;
            int k = e / DOUT, n = e % DOUT;
            float w = fcw[e];
            __half h = __float2half_rn(w);
            g_FWH[n * DOUT + k] = h;
            g_FWL[n * DOUT + k] = __float2half_rn(w - __half2float(h));
        } else {
            int t2 = gid - PREP_FC;
            int k = t2 >> 5, lane = t2 & 31;
            if (k >= C1) return;
            float s = 0.f, d = 0.f;
#pragma unroll
            for (int j = 0; j < 4; j++) {
                float w = W2[k * DOUT + j * 32 + lane];
                s += w * a2s[j * 32 + lane];
                d += w * a2d[j * 32 + lane];
            }
#pragma unroll
            for (int o = 16; o > 0; o >>= 1) {
                s += __shfl_down_sync(0xffffffffu, s, o);
                d += __shfl_down_sync(0xffffffffu, d, o);
            }
            if (lane == 0) { g_Q2S[k] = s; g_Q2D[k] = d; }
        }
    }
}

// ---------------- scan: warp-shuffle hierarchy + decoupled lookback -----------
// Also seeds the self-loop edge of each node (ESRT[ROWPTR[n]] = n).
__global__ void k_scan() {
    __shared__ int swarp[32];
    __shared__ int s_boff;
    int* flags = g_DEG + NN;
    int b = blockIdx.x, t = threadIdx.x;
    int wid = t >> 5, lane = t & 31;
    int n = b * 1024 + t;
    int v = (n < NN) ? g_DEG[n] + 1 : 0;

    int x = v;
#pragma unroll
    for (int o = 1; o < 32; o <<= 1) {
        int u = __shfl_up_sync(0xffffffffu, x, o);
        if (lane >= o) x += u;
    }
    if (lane == 31) swarp[wid] = x;
    __syncthreads();
    if (wid == 0) {
        int y = swarp[lane];
#pragma unroll
        for (int o = 1; o < 32; o <<= 1) {
            int u = __shfl_up_sync(0xffffffffu, y, o);
            if (lane >= o) y += u;
        }
        swarp[lane] = y;
    }
    __syncthreads();
    int incl = x + (wid > 0 ? swarp[wid - 1] : 0);

    if (t == 1023) {
        g_BSUM[b] = incl;
        __threadfence();
        atomicExch(&flags[b], 1);
    }
    if (t < 32) {
        int p = 0;
        if (t < b) {
            while (atomicAdd(&flags[t], 0) == 0) {}
            p = g_BSUM[t];
        }
#pragma unroll
        for (int o = 16; o > 0; o >>= 1)
            p += __shfl_down_sync(0xffffffffu, p, o);
        if (t == 0) s_boff = p;
    }
    __syncthreads();
    if (n < NN) {
        int r = incl - v + s_boff;
        g_ROWPTR[n] = r;
        g_ESRT[r] = n;           // self-loop placed at row start
        g_ROWCUR[n] = r + 1;
    }
    if (b == 19 && t == 1023) g_ROWPTR[NN] = ETOT;
    if (n < BG * DOUT) g_X2E[(size_t)NN * DOUT + n] = 0.f;
}

__global__ void k_scatter(const int* __restrict__ esrc, const int* __restrict__ edst) {
    int e = blockIdx.x * blockDim.x + threadIdx.x;
    if (e >= EE) return;
    int pos = atomicAdd(&g_ROWCUR[edst[e]], 1);
    g_ESRT[pos] = esrc[e];
}

// ---------------- layer-1 aggregation: uint4 gather, 2 shfls/edge -------------
__global__ __launch_bounds__(256)
void k_agg1(const float* __restrict__ b1) {
    int lane = threadIdx.x & 31;
    int n = (blockIdx.x * blockDim.x + threadIdx.x) >> 5;
    if (n >= NN) return;
    int p0 = g_ROWPTR[n], p1 = g_ROWPTR[n + 1];
    float sd = (lane < NH) ? g_S1D[n * NH + lane] : 0.f;
    const int hA = lane >> 2;
    const int hB = 8 + (lane >> 2);

    float2 accA[4], accB[4];
#pragma unroll
    for (int j = 0; j < 4; j++) { accA[j] = make_float2(0.f, 0.f); accB[j] = make_float2(0.f, 0.f); }
    float denom = 0.f;

    int s = g_ESRT[p0];
    float sc = (lane < NH) ? g_S1S[s * NH + lane] : 0.f;
    for (int k = p0; k < p1; k++) {
        int s_cur = s;
        float sc_cur = sc;
        if (k + 1 < p1) {
            s = g_ESRT[k + 1];
            sc = (lane < NH) ? g_S1S[s * NH + lane] : 0.f;
        }
        float ex = (lane < NH) ? __expf(leakyf(sc_cur + sd)) : 0.f;
        denom += ex;
        const uint4* row4 = reinterpret_cast<const uint4*>(g_XW1H + (size_t)s_cur * C1);
        uint4 va = row4[lane];
        float aA = __shfl_sync(0xffffffffu, ex, hA);
        float aB = __shfl_sync(0xffffffffu, ex, hB);
        const __half2* ha = reinterpret_cast<const __half2*>(&va);
#pragma unroll
        for (int j = 0; j < 4; j++) {
            float2 f = __half22float2(ha[j]);
            accA[j].x = fmaf(aA, f.x, accA[j].x);
            accA[j].y = fmaf(aA, f.y, accA[j].y);
        }
        if (lane < 8) {
            uint4 vb = row4[32 + lane];
            const __half2* hb = reinterpret_cast<const __half2*>(&vb);
#pragma unroll
            for (int j = 0; j < 4; j++) {
                float2 f = __half22float2(hb[j]);
                accB[j].x = fmaf(aB, f.x, accB[j].x);
                accB[j].y = fmaf(aB, f.y, accB[j].y);
            }
        }
    }

    float dA = fmaxf(__shfl_sync(0xffffffffu, denom, hA), 1e-16f);
    float dB = fmaxf(__shfl_sync(0xffffffffu, denom, hB), 1e-16f);

    float vs = 0.f, vd = 0.f;
    {
        int c0 = 8 * lane;
        float4 bb0 = *reinterpret_cast<const float4*>(b1 + c0);
        float4 bb1 = *reinterpret_cast<const float4*>(b1 + c0 + 4);
        float o0 = eluf(accA[0].x / dA + bb0.x);
        float o1 = eluf(accA[0].y / dA + bb0.y);
        float o2 = eluf(accA[1].x / dA + bb0.z);
        float o3 = eluf(accA[1].y / dA + bb0.w);
        float o4 = eluf(accA[2].x / dA + bb1.x);
        float o5 = eluf(accA[2].y / dA + bb1.y);
        float o6 = eluf(accA[3].x / dA + bb1.z);
        float o7 = eluf(accA[3].y / dA + bb1.w);
        *reinterpret_cast<uint4*>(g_X1H + (size_t)n * C1 + c0) =
            pack8h(o0, o1, o2, o3, o4, o5, o6, o7);
        float4 q0 = *reinterpret_cast<const float4*>(g_Q2S + c0);
        float4 q1 = *reinterpret_cast<const float4*>(g_Q2S + c0 + 4);
        float4 r0 = *reinterpret_cast<const float4*>(g_Q2D + c0);
        float4 r1 = *reinterpret_cast<const float4*>(g_Q2D + c0 + 4);
        vs += o0*q0.x + o1*q0.y + o2*q0.z + o3*q0.w + o4*q1.x + o5*q1.y + o6*q1.z + o7*q1.w;
        vd += o0*r0.x + o1*r0.y + o2*r0.z + o3*r0.w + o4*r1.x + o5*r1.y + o6*r1.z + o7*r1.w;
    }
    if (lane < 8) {
        int c0 = 256 + 8 * lane;
        float4 bb0 = *reinterpret_cast<const float4*>(b1 + c0);
        float4 bb1 = *reinterpret_cast<const float4*>(b1 + c0 + 4);
        float o0 = eluf(accB[0].x / dB + bb0.x);
        float o1 = eluf(accB[0].y / dB + bb0.y);
        float o2 = eluf(accB[1].x / dB + bb0.z);
        float o3 = eluf(accB[1].y / dB + bb0.w);
        float o4 = eluf(accB[2].x / dB + bb1.x);
        float o5 = eluf(accB[2].y / dB + bb1.y);
        float o6 = eluf(accB[3].x / dB + bb1.z);
        float o7 = eluf(accB[3].y / dB + bb1.w);
        *reinterpret_cast<uint4*>(g_X1H + (size_t)n * C1 + c0) =
            pack8h(o0, o1, o2, o3, o4, o5, o6, o7);
        float4 q0 = *reinterpret_cast<const float4*>(g_Q2S + c0);
        float4 q1 = *reinterpret_cast<const float4*>(g_Q2S + c0 + 4);
        float4 r0 = *reinterpret_cast<const float4*>(g_Q2D + c0);
        float4 r1 = *reinterpret_cast<const float4*>(g_Q2D + c0 + 4);
        vs += o0*q0.x + o1*q0.y + o2*q0.z + o3*q0.w + o4*q1.x + o5*q1.y + o6*q1.z + o7*q1.w;
        vd += o0*r0.x + o1*r0.y + o2*r0.z + o3*r0.w + o4*r1.x + o5*r1.y + o6*r1.z + o7*r1.w;
    }
#pragma unroll
    for (int o = 16; o > 0; o >>= 1) {
        vs += __shfl_down_sync(0xffffffffu, vs, o);
        vd += __shfl_down_sync(0xffffffffu, vd, o);
    }
    if (lane == 0) { g_S2S[n] = vs; g_S2D[n] = vd; }
}

// ---------------- layer-2 aggregation: 2 edges/iter + smem-staged pool --------
__global__ __launch_bounds__(256)
void k_agg2(const float* __restrict__ b2) {
    __shared__ int smax[DOUT];
    int tid = threadIdx.x;
    int lane = tid & 31;
    int n = (blockIdx.x * blockDim.x + tid) >> 5;
    if (tid < DOUT) smax[tid] = 0;
    __syncthreads();

    if (n < NN) {
        int p0 = g_ROWPTR[n], p1 = g_ROWPTR[n + 1];
        float sd = g_S2D[n];
        int half = lane >> 4, li = lane & 15;

        float2 acc[4];
#pragma unroll
        for (int j = 0; j < 4; j++) acc[j] = make_float2(0.f, 0.f);
        float denom = 0.f;

        for (int k = p0; k < p1; k += 2) {
            int kk = k + half;
            int kc = (kk < p1) ? kk : p1 - 1;
            int s = g_ESRT[kc];
            float sc = g_S2S[s];
            float ex = (kk < p1) ? __expf(leakyf(sc + sd)) : 0.f;
            denom += ex;
            const uint4* row4 = reinterpret_cast<const uint4*>(g_XW2H + (size_t)s * DOUT);
            uint4 v = row4[li];
            const __half2* vh = reinterpret_cast<const __half2*>(&v);
#pragma unroll
            for (int j = 0; j < 4; j++) {
                float2 f = __half22float2(vh[j]);
                acc[j].x = fmaf(ex, f.x, acc[j].x);
                acc[j].y = fmaf(ex, f.y, acc[j].y);
            }
        }
        denom += __shfl_xor_sync(0xffffffffu, denom, 16);
#pragma unroll
        for (int j = 0; j < 4; j++) {
            acc[j].x += __shfl_xor_sync(0xffffffffu, acc[j].x, 16);
            acc[j].y += __shfl_xor_sync(0xffffffffu, acc[j].y, 16);
        }
        float dn = fmaxf(denom, 1e-16f);

        if (half == 0) {
            int c0 = 8 * li;
            float4 bb0 = *reinterpret_cast<const float4*>(b2 + c0);
            float4 bb1 = *reinterpret_cast<const float4*>(b2 + c0 + 4);
            float4 w0, w1;
            w0.x = fmaxf(acc[0].x / dn + bb0.x, 0.f);
            w0.y = fmaxf(acc[0].y / dn + bb0.y, 0.f);
            w0.z = fmaxf(acc[1].x / dn + bb0.z, 0.f);
            w0.w = fmaxf(acc[1].y / dn + bb0.w, 0.f);
            w1.x = fmaxf(acc[2].x / dn + bb1.x, 0.f);
            w1.y = fmaxf(acc[2].y / dn + bb1.y, 0.f);
            w1.z = fmaxf(acc[3].x / dn + bb1.z, 0.f);
            w1.w = fmaxf(acc[3].y / dn + bb1.w, 0.f);
            *reinterpret_cast<float4*>(g_X2E + (size_t)n * DOUT + c0)     = w0;
            *reinterpret_cast<float4*>(g_X2E + (size_t)n * DOUT + c0 + 4) = w1;
            atomicMax(&smax[c0 + 0], __float_as_int(w0.x));
            atomicMax(&smax[c0 + 1], __float_as_int(w0.y));
            atomicMax(&smax[c0 + 2], __float_as_int(w0.z));
            atomicMax(&smax[c0 + 3], __float_as_int(w0.w));
            atomicMax(&smax[c0 + 4], __float_as_int(w1.x));
            atomicMax(&smax[c0 + 5], __float_as_int(w1.y));
            atomicMax(&smax[c0 + 6], __float_as_int(w1.z));
            atomicMax(&smax[c0 + 7], __float_as_int(w1.w));
        }
    }
    __syncthreads();
    if (tid < DOUT) {
        int grow = NN + (blockIdx.x * 8) / PERN;
        atomicMax(reinterpret_cast<int*>(g_X2E + (size_t)grow * DOUT) + tid, smax[tid]);
    }
}

// ============================================================================
extern "C" void kernel_launch(void* const* d_in, const int* in_sizes, int n_in,
                              void* d_out, int out_size) {
    const float* feats = (const float*)d_in[0];
    const int*   ei    = (const int*)d_in[1];
    const int*   esrc  = ei;
    const int*   edst  = ei + EE;
    const float* W1  = (const float*)d_in[4];
    const float* a1s = (const float*)d_in[5];
    const float* a1d = (const float*)d_in[6];
    const float* b1  = (const float*)d_in[7];
    const float* W2  = (const float*)d_in[8];
    const float* a2s = (const float*)d_in[9];
    const float* a2d = (const float*)d_in[10];
    const float* b2  = (const float*)d_in[11];
    const float* fcw = (const float*)d_in[12];
    const float* fcb = (const float*)d_in[13];
    float* out = (float*)d_out;

    void *pX1H, *pX2E, *pB1E, *pDEG, *pW2H, *pW2L, *pFWH, *pFWL;
    cudaGetSymbolAddress(&pX1H, g_X1H);
    cudaGetSymbolAddress(&pX2E, g_X2E);
    cudaGetSymbolAddress(&pB1E, g_B1E);
    cudaGetSymbolAddress(&pDEG, g_DEG);
    cudaGetSymbolAddress(&pW2H, g_W2H);
    cudaGetSymbolAddress(&pW2L, g_W2L);
    cudaGetSymbolAddress(&pFWH, g_FWH);
    cudaGetSymbolAddress(&pFWL, g_FWL);

    static cudaStream_t s2 = nullptr;
    static cudaEvent_t evF = nullptr, evJ = nullptr;
    if (!s2) {
        cudaStreamCreateWithFlags(&s2, cudaStreamNonBlocking);
        cudaEventCreateWithFlags(&evF, cudaEventDisableTiming);
        cudaEventCreateWithFlags(&evJ, cudaEventDisableTiming);
    }

    const int WB = 256;
    int warpBlocks = (NN * 32 + WB - 1) / WB;

    cudaMemsetAsync(pDEG, 0, (NN + 32) * sizeof(int));

    k_pre<<<PRE_BLKS, 352>>>(edst, W1, a1s, a1d, W2, fcw, a2s, a2d);

    cudaEventRecord(evF, 0);
    cudaStreamWaitEvent(s2, evF, 0);

    dim3 g1((NN + 127) / 128, (C1E + 127) / 128);
    k_tgemm1<<<g1, 256, 0, s2>>>(feats, (const float*)pB1E, NN, C1E, FIN);

    k_scan<<<20, 1024>>>();
    k_scatter<<<(EE + 255) / 256, 256>>>(esrc, edst);

    cudaEventRecord(evJ, s2);
    cudaStreamWaitEvent(0, evJ, 0);

    k_agg1<<<warpBlocks, WB>>>(b1);

    k_hgemm<4, __half><<<(NN + 127) / 128, 256>>>(
        (const __half*)pX1H, (const __half*)pW2H, (const __half*)pW2L,
        nullptr, nullptr, NN, C1);

    k_agg2<<<warpBlocks, WB>>>(b2);

    k_hgemm<1, float><<<(NN + BG + 127) / 128, 256>>>(
        (const float*)pX2E, (const __half*)pFWH, (const __half*)pFWL,
        fcb, out, NN + BG, DOUT);
}